// round 9
// baseline (speedup 1.0000x reference)
#include <cuda_runtime.h>
#include <cuda_bf16.h>
#include <stdint.h>
#include <math.h>

#define B      512
#define H      512
#define TENC   512
#define TDEC   128
#define NTHREADS 256
#define NCHUNK 24                    // 3 split-parts * (512/64) K-chunks
#define NSTAGE 4
#define STAGE_BYTES 16384            // A 8KB + B 8KB per stage (64x64 tile)
#define SMEM_DYN (NSTAGE * STAGE_BYTES + 1024)

// ---------------- persistent device state (no allocation allowed) ----------
static __device__ __align__(16) __nv_bfloat16 g_hhi0[B * H];
static __device__ __align__(16) __nv_bfloat16 g_hhi1[B * H];
static __device__ __align__(16) __nv_bfloat16 g_hlo0[B * H];
static __device__ __align__(16) __nv_bfloat16 g_hlo1[B * H];
static __device__ float g_c[B * H];
static __device__ float g_x[B];
static __device__ __align__(16) __nv_bfloat16 g_whi_e[2048 * 512];
static __device__ __align__(16) __nv_bfloat16 g_wlo_e[2048 * 512];
static __device__ __align__(16) __nv_bfloat16 g_whi_d[2048 * 512];
static __device__ __align__(16) __nv_bfloat16 g_wlo_d[2048 * 512];

// ---------------- helpers ----------------------------------------------------
__device__ __forceinline__ uint32_t smem_u32(const void* p) {
    uint32_t a;
    asm("{ .reg .u64 t; cvta.to.shared.u64 t, %1; cvt.u32.u64 %0, t; }"
        : "=r"(a) : "l"(p));
    return a;
}

__device__ __forceinline__ void cp16(uint32_t dst, const void* src) {
    asm volatile("cp.async.cg.shared.global [%0], [%1], 16;"
                 :: "r"(dst), "l"(src));
}
__device__ __forceinline__ void cp_commit() {
    asm volatile("cp.async.commit_group;" ::: "memory");
}
__device__ __forceinline__ void cp_wait2() {
    asm volatile("cp.async.wait_group 2;" ::: "memory");
}

__device__ __forceinline__ void ldsm_x4(uint32_t& r0, uint32_t& r1,
                                        uint32_t& r2, uint32_t& r3,
                                        uint32_t addr) {
    asm volatile("ldmatrix.sync.aligned.m8n8.x4.shared.b16 {%0,%1,%2,%3}, [%4];"
                 : "=r"(r0), "=r"(r1), "=r"(r2), "=r"(r3) : "r"(addr));
}

__device__ __forceinline__ void mma_bf16(float* c, const uint32_t* a,
                                         uint32_t b0, uint32_t b1) {
    asm volatile(
        "mma.sync.aligned.m16n8k16.row.col.f32.bf16.bf16.f32 "
        "{%0,%1,%2,%3}, {%4,%5,%6,%7}, {%8,%9}, {%0,%1,%2,%3};"
        : "+f"(c[0]), "+f"(c[1]), "+f"(c[2]), "+f"(c[3])
        : "r"(a[0]), "r"(a[1]), "r"(a[2]), "r"(a[3]), "r"(b0), "r"(b1));
}

__device__ __forceinline__ float sigf(float x) {
    return 1.0f / (1.0f + __expf(-x));
}

// ---------------- prologue kernels -------------------------------------------
// Repack W (2048,512): packed row n' = nt*64 + g*16 + jl  <->  n = g*512 + nt*16 + jl
__global__ void pack_w_kernel(const float* __restrict__ W,
                              __nv_bfloat16* __restrict__ whi,
                              __nv_bfloat16* __restrict__ wlo) {
    int idx = blockIdx.x * 256 + threadIdx.x;    // n'*512 + k
    int np = idx >> 9, k = idx & 511;
    int nt = np >> 6, r = np & 63;
    int n = (r >> 4) * 512 + nt * 16 + (r & 15);
    float w = W[n * 512 + k];
    __nv_bfloat16 hi = __float2bfloat16_rn(w);
    whi[idx] = hi;
    wlo[idx] = __float2bfloat16_rn(w - __bfloat162float(hi));
}

__global__ void zero_state_kernel() {
    int i = blockIdx.x * 256 + threadIdx.x;
    if (i < B * H) {
        g_hhi0[i] = __float2bfloat16(0.0f);
        g_hlo0[i] = __float2bfloat16(0.0f);
        g_c[i] = 0.0f;
    }
}

__global__ void seed_x_kernel(const float* __restrict__ inputs) {
    int b = blockIdx.x * 256 + threadIdx.x;
    if (b < B) g_x[b] = inputs[b * TENC + (TENC - 1)];
}

// ---------------- fused LSTM step (HMMA + 4-stage cp.async, 64x64 tile) ------
// CTA (nt, mt): batch rows [mt*64,+64), packed z-cols [nt*64,+64)
// (= 4 gates x 16 hidden units jh in [nt*16,+16)).
// Split-3 bf16: hh*Wh + hh*Wl + hl*Wh as one K=1536 accumulation.
// xmode==1 (decoder t>=1): x = lin(h_in) computed inline; also writes out[:,tprev].
__global__ void __launch_bounds__(NTHREADS, 2)
lstm_step_kernel(const __nv_bfloat16* __restrict__ hhi,
                 const __nv_bfloat16* __restrict__ hlo,
                 __nv_bfloat16* __restrict__ hhi_out,
                 __nv_bfloat16* __restrict__ hlo_out,
                 const __nv_bfloat16* __restrict__ whi,
                 const __nv_bfloat16* __restrict__ wlo,
                 const float* __restrict__ Wih,
                 const float* __restrict__ bias,
                 const float* __restrict__ x_base,
                 int x_stride, int x_off,
                 int xmode,
                 const float* __restrict__ linW,
                 const float* __restrict__ linb,
                 float* __restrict__ outp,
                 int tprev)
{
    extern __shared__ char dsmem[];
    __shared__ float xs[64];
    uint32_t raw = smem_u32(dsmem);
    uint32_t sb  = (raw + 1023) & ~1023u;
    char* sp     = dsmem + (sb - raw);
    float* zs    = (float*)sp;       // 64 x 68 f32 (17.4KB), reuses stages 0-1

    const int tid  = threadIdx.x;
    const int wid  = tid >> 5;
    const int lane = tid & 31;
    const int wm   = wid >> 1;        // warp m-tile 0..3 (16 rows each)
    const int wn   = wid & 1;         // warp n-tile 0..1 (32 cols each)
    const int nt   = blockIdx.x;      // 0..31
    const int mt   = blockIdx.y;      // 0..7
    const int brow0 = mt * 64;

    // ---- global->smem staging mapping (16B per slot, swizzled) --------------
    const int gr  = tid >> 3;                 // 0..31 (rows gr, gr+32)
    const int gce = (tid & 7) * 8;            // element col (8 bf16 = 16B)
    uint32_t so[2];
#pragma unroll
    for (int i = 0; i < 2; i++) {
        int row = gr + 32 * i;
        so[i] = (uint32_t)row * 128u + (((uint32_t)gce * 2) ^ (uint32_t)((row & 7) << 4));
    }

    // ---- ldmatrix lane addressing (per warp) --------------------------------
    const int lrow = lane & 15;
    const uint32_t kb2 = (uint32_t)((lane >> 4) * 16);   // byte offset of k-half
    uint32_t aoff, axor, boff[2], bxor[2];
    {
        int r = wm * 16 + lrow;
        aoff = (uint32_t)r * 128u;
        axor = (uint32_t)((r & 7) << 4);
    }
#pragma unroll
    for (int nb = 0; nb < 2; nb++) {
        int r = wn * 32 + nb * 16 + lrow;
        boff[nb] = (uint32_t)r * 128u;
        bxor[nb] = (uint32_t)((r & 7) << 4);
    }

    float acc[4][4];
#pragma unroll
    for (int ni = 0; ni < 4; ni++)
#pragma unroll
        for (int q = 0; q < 4; q++) acc[ni][q] = 0.0f;

    // ---- issue helper --------------------------------------------------------
    auto issue_chunk = [&](int kc) {
        const int part = kc >> 3;             // 0: hh*wh, 1: hh*wl, 2: hl*wh
        const int koff = (kc & 7) * 64;
        const __nv_bfloat16* aS = (part < 2 ? hhi : hlo);
        const __nv_bfloat16* bS = (part == 1 ? wlo : whi);
        const uint32_t ab = sb + (uint32_t)(kc & (NSTAGE - 1)) * STAGE_BYTES;
        const uint32_t bb = ab + 8192u;
#pragma unroll
        for (int i = 0; i < 2; i++)
            cp16(ab + so[i], aS + (size_t)(brow0 + gr + 32 * i) * 512 + koff + gce);
#pragma unroll
        for (int i = 0; i < 2; i++)
            cp16(bb + so[i], bS + (size_t)(nt * 64 + gr + 32 * i) * 512 + koff + gce);
        cp_commit();
    };

    // ---- prologue: fill 3 stages ---------------------------------------------
    issue_chunk(0);
    issue_chunk(1);
    issue_chunk(2);

    // ---- main K loop ----------------------------------------------------------
    for (int k = 0; k < NCHUNK; k++) {
        cp_wait2();          // stage k complete (groups always advance 1/iter)
        __syncthreads();     // all warps done with chunk k-1; stage (k+3)&3 free

        if (k + 3 < NCHUNK) issue_chunk(k + 3);
        else                cp_commit();      // keep group count advancing

        const uint32_t au = sb + (uint32_t)(k & (NSTAGE - 1)) * STAGE_BYTES;
        const uint32_t bu = au + 8192u;
#pragma unroll
        for (int s = 0; s < 4; s++) {
            const uint32_t kb = (uint32_t)(s * 32);    // k0*2 bytes
            uint32_t af[4];
            ldsm_x4(af[0], af[1], af[2], af[3],
                    au + aoff + ((kb + kb2) ^ axor));
            uint32_t bq[4][2];
#pragma unroll
            for (int nb = 0; nb < 2; nb++) {
                uint32_t q0, q1, q2, q3;
                ldsm_x4(q0, q1, q2, q3,
                        bu + boff[nb] + ((kb + kb2) ^ bxor[nb]));
                bq[nb * 2 + 0][0] = q0; bq[nb * 2 + 0][1] = q2;
                bq[nb * 2 + 1][0] = q1; bq[nb * 2 + 1][1] = q3;
            }
#pragma unroll
            for (int ni = 0; ni < 4; ni++)
                mma_bf16(acc[ni], af, bq[ni][0], bq[ni][1]);
        }
    }
    __syncthreads();   // all compute done before zs overwrites stages 0-1

    // ---- accum -> smem z tile (stride 68 to dodge bank conflicts) -----------
    {
        const int g  = lane >> 2;
        const int t2 = (lane & 3) * 2;
#pragma unroll
        for (int ni = 0; ni < 4; ni++) {
            const int row = wm * 16 + g;
            const int col = wn * 32 + ni * 8 + t2;
            *(float2*)(zs + row * 68 + col) = make_float2(acc[ni][0], acc[ni][1]);
            *(float2*)(zs + (row + 8) * 68 + col) = make_float2(acc[ni][2], acc[ni][3]);
        }
    }

    // ---- inline decoder feedback: x = lin(h_in), out[:,tprev] ---------------
    if (xmode) {
        const int ml = tid >> 2;               // 0..63
        const int q  = tid & 3;                // K quarter
        const int b  = brow0 + ml;
        const __nv_bfloat16* ph = hhi + (size_t)b * 512 + q * 128;
        const __nv_bfloat16* pl = hlo + (size_t)b * 512 + q * 128;
        const float* pw = linW + q * 128;
        float s = 0.0f;
#pragma unroll
        for (int i = 0; i < 16; i++) {
            uint4 uh = *(const uint4*)(ph + i * 8);
            uint4 ul = *(const uint4*)(pl + i * 8);
            float4 w0 = *(const float4*)(pw + i * 8);
            float4 w1 = *(const float4*)(pw + i * 8 + 4);
            const __nv_bfloat162* h2 = (const __nv_bfloat162*)&uh;
            const __nv_bfloat162* l2 = (const __nv_bfloat162*)&ul;
            float2 a0 = __bfloat1622float2(h2[0]), c0 = __bfloat1622float2(l2[0]);
            float2 a1 = __bfloat1622float2(h2[1]), c1 = __bfloat1622float2(l2[1]);
            float2 a2 = __bfloat1622float2(h2[2]), c2 = __bfloat1622float2(l2[2]);
            float2 a3 = __bfloat1622float2(h2[3]), c3 = __bfloat1622float2(l2[3]);
            s = fmaf(a0.x + c0.x, w0.x, s);
            s = fmaf(a0.y + c0.y, w0.y, s);
            s = fmaf(a1.x + c1.x, w0.z, s);
            s = fmaf(a1.y + c1.y, w0.w, s);
            s = fmaf(a2.x + c2.x, w1.x, s);
            s = fmaf(a2.y + c2.y, w1.y, s);
            s = fmaf(a3.x + c3.x, w1.z, s);
            s = fmaf(a3.y + c3.y, w1.w, s);
        }
        s += __shfl_xor_sync(0xffffffffu, s, 1);
        s += __shfl_xor_sync(0xffffffffu, s, 2);
        if (q == 0) {
            const float v = s + linb[0];
            xs[ml] = v;
            if (nt == 0) outp[(size_t)b * TDEC + tprev] = v;
        }
    }
    __syncthreads();

    // ---- gate pass: thread handles 4 (b, jh) pairs ---------------------------
    {
        const int ml  = tid >> 2;                 // 0..63
        const int jl0 = (tid & 3) * 4;
        const int b   = brow0 + ml;
        const float xv = xmode ? xs[ml] : x_base[b * x_stride + x_off];
#pragma unroll
        for (int j = 0; j < 4; j++) {
            const int jl = jl0 + j;
            const int jh = nt * 16 + jl;
            const float zi = zs[ml * 68 +      jl] + xv * __ldg(&Wih[jh])        + __ldg(&bias[jh]);
            const float zf = zs[ml * 68 + 16 + jl] + xv * __ldg(&Wih[512 + jh])  + __ldg(&bias[512 + jh]);
            const float zg = zs[ml * 68 + 32 + jl] + xv * __ldg(&Wih[1024 + jh]) + __ldg(&bias[1024 + jh]);
            const float zo = zs[ml * 68 + 48 + jl] + xv * __ldg(&Wih[1536 + jh]) + __ldg(&bias[1536 + jh]);
            const int idx = b * H + jh;
            const float cn = sigf(zf) * g_c[idx] + sigf(zi) * tanhf(zg);
            g_c[idx] = cn;
            const float hv = sigf(zo) * tanhf(cn);
            const __nv_bfloat16 hh = __float2bfloat16_rn(hv);
            hhi_out[idx] = hh;
            hlo_out[idx] = __float2bfloat16_rn(hv - __bfloat162float(hh));
        }
    }
}

// ---------------- final decoder output (t = TDEC-1) ---------------------------
__global__ void __launch_bounds__(256)
dec_out_kernel(const __nv_bfloat16* __restrict__ hhi,
               const __nv_bfloat16* __restrict__ hlo,
               const float* __restrict__ linW,
               const float* __restrict__ linb,
               float* __restrict__ out, int t)
{
    const int b    = blockIdx.x * 8 + (threadIdx.x >> 5);
    const int lane = threadIdx.x & 31;
    const size_t base = (size_t)b * H;
    float s = 0.0f;
#pragma unroll
    for (int k = lane; k < H; k += 32) {
        float hv = __bfloat162float(hhi[base + k]) + __bfloat162float(hlo[base + k]);
        s = fmaf(hv, linW[k], s);
    }
#pragma unroll
    for (int o = 16; o; o >>= 1)
        s += __shfl_xor_sync(0xffffffffu, s, o);
    if (lane == 0)
        out[b * TDEC + t] = s + linb[0];
}

// ---------------- launch ------------------------------------------------------
extern "C" void kernel_launch(void* const* d_in, const int* in_sizes, int n_in,
                              void* d_out, int out_size)
{
    (void)in_sizes; (void)n_in; (void)out_size;
    const float* inputs = (const float*)d_in[0];
    // d_in[1] = targets (unused: teacher_forcing_ratio == 0)
    const float* encWih = (const float*)d_in[2];
    const float* encWhh = (const float*)d_in[3];
    const float* encB   = (const float*)d_in[4];
    const float* decWih = (const float*)d_in[5];
    const float* decWhh = (const float*)d_in[6];
    const float* decB   = (const float*)d_in[7];
    const float* linW   = (const float*)d_in[8];
    const float* linB   = (const float*)d_in[9];
    float* out = (float*)d_out;

    cudaFuncSetAttribute(lstm_step_kernel,
                         cudaFuncAttributeMaxDynamicSharedMemorySize, SMEM_DYN);

    __nv_bfloat16 *hhi[2], *hlo[2], *whiE, *wloE, *whiD, *wloD;
    float* xp;
    cudaGetSymbolAddress((void**)&hhi[0], g_hhi0);
    cudaGetSymbolAddress((void**)&hhi[1], g_hhi1);
    cudaGetSymbolAddress((void**)&hlo[0], g_hlo0);
    cudaGetSymbolAddress((void**)&hlo[1], g_hlo1);
    cudaGetSymbolAddress((void**)&whiE, g_whi_e);
    cudaGetSymbolAddress((void**)&wloE, g_wlo_e);
    cudaGetSymbolAddress((void**)&whiD, g_whi_d);
    cudaGetSymbolAddress((void**)&wloD, g_wlo_d);
    cudaGetSymbolAddress((void**)&xp, g_x);

    pack_w_kernel<<<4096, 256>>>(encWhh, whiE, wloE);
    pack_w_kernel<<<4096, 256>>>(decWhh, whiD, wloD);
    zero_state_kernel<<<(B * H) / 256, 256>>>();

    const dim3 grid(32, 8);   // nt x mt = 256 CTAs

    int s = 0;
    for (int t = 0; t < TENC; t++, s++) {
        lstm_step_kernel<<<grid, NTHREADS, SMEM_DYN>>>(
            hhi[s & 1], hlo[s & 1], hhi[(s & 1) ^ 1], hlo[(s & 1) ^ 1],
            whiE, wloE, encWih, encB, inputs, TENC, t,
            0, linW, linB, out, 0);
    }

    seed_x_kernel<<<2, 256>>>(inputs);

    for (int t = 0; t < TDEC; t++, s++) {
        const int xmode = (t > 0) ? 1 : 0;
        lstm_step_kernel<<<grid, NTHREADS, SMEM_DYN>>>(
            hhi[s & 1], hlo[s & 1], hhi[(s & 1) ^ 1], hlo[(s & 1) ^ 1],
            whiD, wloD, decWih, decB, xp, 1, 0,
            xmode, linW, linB, out, t - 1);
    }

    // final column: out[:, TDEC-1] = lin(h_final)
    dec_out_kernel<<<B / 8, 256>>>(hhi[s & 1], hlo[s & 1], linW, linB,
                                   out, TDEC - 1);
}

// round 10
// speedup vs baseline: 1.0295x; 1.0295x over previous
#include <cuda_runtime.h>
#include <cuda_bf16.h>
#include <stdint.h>
#include <math.h>

#define B      512
#define H      512
#define TENC   512
#define TDEC   128
#define NTHREADS 256
#define NCHUNK 24                    // 3 split-parts * (512/64) K-chunks
#define NITER  12                    // 2 chunks per iteration
#define NSTAGE 6
#define STAGE_BYTES 16384            // A 8KB + B 8KB per stage (64x64 tile)
#define SMEM_DYN (NSTAGE * STAGE_BYTES + 1024)

// ---------------- persistent device state (no allocation allowed) ----------
static __device__ __align__(16) __nv_bfloat16 g_hhi0[B * H];
static __device__ __align__(16) __nv_bfloat16 g_hhi1[B * H];
static __device__ __align__(16) __nv_bfloat16 g_hlo0[B * H];
static __device__ __align__(16) __nv_bfloat16 g_hlo1[B * H];
static __device__ float g_c[B * H];
static __device__ float g_x[B];
static __device__ __align__(16) __nv_bfloat16 g_whi_e[2048 * 512];
static __device__ __align__(16) __nv_bfloat16 g_wlo_e[2048 * 512];
static __device__ __align__(16) __nv_bfloat16 g_whi_d[2048 * 512];
static __device__ __align__(16) __nv_bfloat16 g_wlo_d[2048 * 512];

// ---------------- helpers ----------------------------------------------------
__device__ __forceinline__ uint32_t smem_u32(const void* p) {
    uint32_t a;
    asm("{ .reg .u64 t; cvta.to.shared.u64 t, %1; cvt.u32.u64 %0, t; }"
        : "=r"(a) : "l"(p));
    return a;
}

__device__ __forceinline__ void cp16(uint32_t dst, const void* src) {
    asm volatile("cp.async.cg.shared.global [%0], [%1], 16;"
                 :: "r"(dst), "l"(src));
}
__device__ __forceinline__ void cp_commit() {
    asm volatile("cp.async.commit_group;" ::: "memory");
}
__device__ __forceinline__ void cp_wait1() {
    asm volatile("cp.async.wait_group 1;" ::: "memory");
}

__device__ __forceinline__ void ldsm_x4(uint32_t& r0, uint32_t& r1,
                                        uint32_t& r2, uint32_t& r3,
                                        uint32_t addr) {
    asm volatile("ldmatrix.sync.aligned.m8n8.x4.shared.b16 {%0,%1,%2,%3}, [%4];"
                 : "=r"(r0), "=r"(r1), "=r"(r2), "=r"(r3) : "r"(addr));
}

__device__ __forceinline__ void mma_bf16(float* c, const uint32_t* a,
                                         uint32_t b0, uint32_t b1) {
    asm volatile(
        "mma.sync.aligned.m16n8k16.row.col.f32.bf16.bf16.f32 "
        "{%0,%1,%2,%3}, {%4,%5,%6,%7}, {%8,%9}, {%0,%1,%2,%3};"
        : "+f"(c[0]), "+f"(c[1]), "+f"(c[2]), "+f"(c[3])
        : "r"(a[0]), "r"(a[1]), "r"(a[2]), "r"(a[3]), "r"(b0), "r"(b1));
}

__device__ __forceinline__ float sigf(float x) {
    return 1.0f / (1.0f + __expf(-x));
}
__device__ __forceinline__ float tanhe(float x) {      // 2*sigmoid(2x) - 1
    return __fmaf_rn(2.0f, sigf(2.0f * x), -1.0f);
}

// ---------------- prologue kernels -------------------------------------------
// Repack W (2048,512): packed row n' = nt*64 + g*16 + jl  <->  n = g*512 + nt*16 + jl
__global__ void pack_w_kernel(const float* __restrict__ W,
                              __nv_bfloat16* __restrict__ whi,
                              __nv_bfloat16* __restrict__ wlo) {
    int idx = blockIdx.x * 256 + threadIdx.x;    // n'*512 + k
    int np = idx >> 9, k = idx & 511;
    int nt = np >> 6, r = np & 63;
    int n = (r >> 4) * 512 + nt * 16 + (r & 15);
    float w = W[n * 512 + k];
    __nv_bfloat16 hi = __float2bfloat16_rn(w);
    whi[idx] = hi;
    wlo[idx] = __float2bfloat16_rn(w - __bfloat162float(hi));
}

__global__ void zero_state_kernel() {
    int i = blockIdx.x * 256 + threadIdx.x;
    if (i < B * H) {
        g_hhi0[i] = __float2bfloat16(0.0f);
        g_hlo0[i] = __float2bfloat16(0.0f);
        g_c[i] = 0.0f;
    }
}

__global__ void seed_x_kernel(const float* __restrict__ inputs) {
    int b = blockIdx.x * 256 + threadIdx.x;
    if (b < B) g_x[b] = inputs[b * TENC + (TENC - 1)];
}

// ---------------- fused LSTM step (HMMA + 6-stage cp.async, 64x64 tile) ------
// CTA (nt, mt): batch rows [mt*64,+64), packed z-cols [nt*64,+64)
// (= 4 gates x 16 hidden units jh in [nt*16,+16)).
// Split-3 bf16: hh*Wh + hh*Wl + hl*Wh as one K=1536 accumulation.
// xmode==1 (decoder t>=1): x = lin(h_in) computed inline; also writes out[:,tprev].
__global__ void __launch_bounds__(NTHREADS, 2)
lstm_step_kernel(const __nv_bfloat16* __restrict__ hhi,
                 const __nv_bfloat16* __restrict__ hlo,
                 __nv_bfloat16* __restrict__ hhi_out,
                 __nv_bfloat16* __restrict__ hlo_out,
                 const __nv_bfloat16* __restrict__ whi,
                 const __nv_bfloat16* __restrict__ wlo,
                 const float* __restrict__ Wih,
                 const float* __restrict__ bias,
                 const float* __restrict__ x_base,
                 int x_stride, int x_off,
                 int xmode,
                 const float* __restrict__ linW,
                 const float* __restrict__ linb,
                 float* __restrict__ outp,
                 int tprev)
{
    extern __shared__ char dsmem[];
    __shared__ float xs[64];
    uint32_t raw = smem_u32(dsmem);
    uint32_t sb  = (raw + 1023) & ~1023u;
    char* sp     = dsmem + (sb - raw);
    float* zs    = (float*)sp;       // 64 x 68 f32 (17.4KB), reuses stages 0-2

    const int tid  = threadIdx.x;
    const int wid  = tid >> 5;
    const int lane = tid & 31;
    const int wm   = wid >> 1;        // warp m-tile 0..3 (16 rows each)
    const int wn   = wid & 1;         // warp n-tile 0..1 (32 cols each)
    const int nt   = blockIdx.x;      // 0..31
    const int mt   = blockIdx.y;      // 0..7
    const int brow0 = mt * 64;

    // ---- epilogue prefetches (latency hidden behind the GEMM) ---------------
    const int eml  = tid >> 2;               // 0..63 (batch row in tile)
    const int ejl0 = (tid & 3) * 4;          // 4 consecutive jh per thread
    const int eb   = brow0 + eml;
    const int jh0  = nt * 16 + ejl0;
    const int eidx = eb * H + jh0;
    const float4 cold = *(const float4*)(g_c + eidx);
    const float xpre = xmode ? 0.0f : x_base[eb * x_stride + x_off];

    // ---- global->smem staging mapping (16B per slot, swizzled) --------------
    const int gr  = tid >> 3;                 // 0..31 (rows gr, gr+32)
    const int gce = (tid & 7) * 8;            // element col (8 bf16 = 16B)
    uint32_t so[2];
#pragma unroll
    for (int i = 0; i < 2; i++) {
        int row = gr + 32 * i;
        so[i] = (uint32_t)row * 128u + (((uint32_t)gce * 2) ^ (uint32_t)((row & 7) << 4));
    }

    // ---- ldmatrix lane addressing (per warp) --------------------------------
    const int lrow = lane & 15;
    const uint32_t kb2 = (uint32_t)((lane >> 4) * 16);   // byte offset of k-half
    uint32_t aoff, axor, boff[2], bxor[2];
    {
        int r = wm * 16 + lrow;
        aoff = (uint32_t)r * 128u;
        axor = (uint32_t)((r & 7) << 4);
    }
#pragma unroll
    for (int nb = 0; nb < 2; nb++) {
        int r = wn * 32 + nb * 16 + lrow;
        boff[nb] = (uint32_t)r * 128u;
        bxor[nb] = (uint32_t)((r & 7) << 4);
    }

    float acc[4][4];
#pragma unroll
    for (int ni = 0; ni < 4; ni++)
#pragma unroll
        for (int q = 0; q < 4; q++) acc[ni][q] = 0.0f;

    // ---- issue one chunk (no commit) ----------------------------------------
    auto issue_chunk = [&](int kc) {
        const int part = kc >> 3;             // 0: hh*wh, 1: hh*wl, 2: hl*wh
        const int koff = (kc & 7) * 64;
        const __nv_bfloat16* aS = (part < 2 ? hhi : hlo);
        const __nv_bfloat16* bS = (part == 1 ? wlo : whi);
        const uint32_t ab = sb + (uint32_t)(kc % NSTAGE) * STAGE_BYTES;
        const uint32_t bb = ab + 8192u;
#pragma unroll
        for (int i = 0; i < 2; i++)
            cp16(ab + so[i], aS + (size_t)(brow0 + gr + 32 * i) * 512 + koff + gce);
#pragma unroll
        for (int i = 0; i < 2; i++)
            cp16(bb + so[i], bS + (size_t)(nt * 64 + gr + 32 * i) * 512 + koff + gce);
    };

    // ---- compute one chunk (4 k16 steps) -------------------------------------
    auto compute_chunk = [&](int kc) {
        const uint32_t au = sb + (uint32_t)(kc % NSTAGE) * STAGE_BYTES;
        const uint32_t bu = au + 8192u;
#pragma unroll
        for (int s = 0; s < 4; s++) {
            const uint32_t kb = (uint32_t)(s * 32);    // k0*2 bytes
            uint32_t af[4];
            ldsm_x4(af[0], af[1], af[2], af[3],
                    au + aoff + ((kb + kb2) ^ axor));
            uint32_t bq[4][2];
#pragma unroll
            for (int nb = 0; nb < 2; nb++) {
                uint32_t q0, q1, q2, q3;
                ldsm_x4(q0, q1, q2, q3,
                        bu + boff[nb] + ((kb + kb2) ^ bxor[nb]));
                bq[nb * 2 + 0][0] = q0; bq[nb * 2 + 0][1] = q2;
                bq[nb * 2 + 1][0] = q1; bq[nb * 2 + 1][1] = q3;
            }
#pragma unroll
            for (int ni = 0; ni < 4; ni++)
                mma_bf16(acc[ni], af, bq[ni][0], bq[ni][1]);
        }
    };

    // ---- prologue: 2 groups of 2 chunks each ---------------------------------
    issue_chunk(0); issue_chunk(1); cp_commit();
    issue_chunk(2); issue_chunk(3); cp_commit();

    // ---- main loop: 12 iterations, 2 chunks each, 1 barrier each -------------
    for (int i = 0; i < NITER; i++) {
        cp_wait1();          // group i complete
        __syncthreads();     // data visible; stages for group i+2 free

        if (i + 2 < NITER) {
            issue_chunk(2 * i + 4);
            issue_chunk(2 * i + 5);
        }
        cp_commit();         // exactly one group per iteration (maybe empty)

        compute_chunk(2 * i);
        compute_chunk(2 * i + 1);
    }
    // NOTE: no barrier needed here — zs (stages 0-2) last consumed before the
    // final iteration's barrier; final chunks live in stages 4-5.

    // ---- accum -> smem z tile (stride 68 to dodge bank conflicts) -----------
    {
        const int g  = lane >> 2;
        const int t2 = (lane & 3) * 2;
#pragma unroll
        for (int ni = 0; ni < 4; ni++) {
            const int row = wm * 16 + g;
            const int col = wn * 32 + ni * 8 + t2;
            *(float2*)(zs + row * 68 + col) = make_float2(acc[ni][0], acc[ni][1]);
            *(float2*)(zs + (row + 8) * 68 + col) = make_float2(acc[ni][2], acc[ni][3]);
        }
    }

    // ---- inline decoder feedback: x = lin(h_in), out[:,tprev] ---------------
    if (xmode) {
        const int ml = tid >> 2;               // 0..63
        const int q  = tid & 3;                // K quarter
        const int b  = brow0 + ml;
        const __nv_bfloat16* ph = hhi + (size_t)b * 512 + q * 128;
        const __nv_bfloat16* pl = hlo + (size_t)b * 512 + q * 128;
        const float* pw = linW + q * 128;
        float s = 0.0f;
#pragma unroll
        for (int i = 0; i < 16; i++) {
            uint4 uh = *(const uint4*)(ph + i * 8);
            uint4 ul = *(const uint4*)(pl + i * 8);
            float4 w0 = *(const float4*)(pw + i * 8);
            float4 w1 = *(const float4*)(pw + i * 8 + 4);
            const __nv_bfloat162* h2 = (const __nv_bfloat162*)&uh;
            const __nv_bfloat162* l2 = (const __nv_bfloat162*)&ul;
            float2 a0 = __bfloat1622float2(h2[0]), c0 = __bfloat1622float2(l2[0]);
            float2 a1 = __bfloat1622float2(h2[1]), c1 = __bfloat1622float2(l2[1]);
            float2 a2 = __bfloat1622float2(h2[2]), c2 = __bfloat1622float2(l2[2]);
            float2 a3 = __bfloat1622float2(h2[3]), c3 = __bfloat1622float2(l2[3]);
            s = fmaf(a0.x + c0.x, w0.x, s);
            s = fmaf(a0.y + c0.y, w0.y, s);
            s = fmaf(a1.x + c1.x, w0.z, s);
            s = fmaf(a1.y + c1.y, w0.w, s);
            s = fmaf(a2.x + c2.x, w1.x, s);
            s = fmaf(a2.y + c2.y, w1.y, s);
            s = fmaf(a3.x + c3.x, w1.z, s);
            s = fmaf(a3.y + c3.y, w1.w, s);
        }
        s += __shfl_xor_sync(0xffffffffu, s, 1);
        s += __shfl_xor_sync(0xffffffffu, s, 2);
        if (q == 0) {
            const float v = s + linb[0];
            xs[ml] = v;
            if (nt == 0) outp[(size_t)b * TDEC + tprev] = v;
        }
    }
    __syncthreads();

    // ---- gate pass: thread handles 4 consecutive (b, jh) pairs ---------------
    {
        const float xv = xmode ? xs[eml] : xpre;

        float4 wi0 = *(const float4*)(Wih + jh0);
        float4 wi1 = *(const float4*)(Wih + 512 + jh0);
        float4 wi2 = *(const float4*)(Wih + 1024 + jh0);
        float4 wi3 = *(const float4*)(Wih + 1536 + jh0);
        float4 bb0 = *(const float4*)(bias + jh0);
        float4 bb1 = *(const float4*)(bias + 512 + jh0);
        float4 bb2 = *(const float4*)(bias + 1024 + jh0);
        float4 bb3 = *(const float4*)(bias + 1536 + jh0);

        float zi[4], zf[4], zg[4], zo[4];
        *(float4*)zi = *(const float4*)(zs + eml * 68 +      ejl0);
        *(float4*)zf = *(const float4*)(zs + eml * 68 + 16 + ejl0);
        *(float4*)zg = *(const float4*)(zs + eml * 68 + 32 + ejl0);
        *(float4*)zo = *(const float4*)(zs + eml * 68 + 48 + ejl0);

        const float* wi0a = (const float*)&wi0;
        const float* wi1a = (const float*)&wi1;
        const float* wi2a = (const float*)&wi2;
        const float* wi3a = (const float*)&wi3;
        const float* bb0a = (const float*)&bb0;
        const float* bb1a = (const float*)&bb1;
        const float* bb2a = (const float*)&bb2;
        const float* bb3a = (const float*)&bb3;
        const float* ca   = (const float*)&cold;

        float cnew[4], hv[4];
#pragma unroll
        for (int j = 0; j < 4; j++) {
            const float vi = zi[j] + xv * wi0a[j] + bb0a[j];
            const float vf = zf[j] + xv * wi1a[j] + bb1a[j];
            const float vg = zg[j] + xv * wi2a[j] + bb2a[j];
            const float vo = zo[j] + xv * wi3a[j] + bb3a[j];
            const float cn = sigf(vf) * ca[j] + sigf(vi) * tanhe(vg);
            cnew[j] = cn;
            hv[j] = sigf(vo) * tanhe(cn);
        }
        *(float4*)(g_c + eidx) = *(float4*)cnew;

        __nv_bfloat162 hh01 = __floats2bfloat162_rn(hv[0], hv[1]);
        __nv_bfloat162 hh23 = __floats2bfloat162_rn(hv[2], hv[3]);
        float lo0 = hv[0] - __bfloat162float(__low2bfloat16(hh01));
        float lo1 = hv[1] - __bfloat162float(__high2bfloat16(hh01));
        float lo2 = hv[2] - __bfloat162float(__low2bfloat16(hh23));
        float lo3 = hv[3] - __bfloat162float(__high2bfloat16(hh23));
        __nv_bfloat162 hl01 = __floats2bfloat162_rn(lo0, lo1);
        __nv_bfloat162 hl23 = __floats2bfloat162_rn(lo2, lo3);
        uint2 hhp, hlp;
        hhp.x = *(uint32_t*)&hh01; hhp.y = *(uint32_t*)&hh23;
        hlp.x = *(uint32_t*)&hl01; hlp.y = *(uint32_t*)&hl23;
        *(uint2*)(hhi_out + eidx) = hhp;
        *(uint2*)(hlo_out + eidx) = hlp;
    }
}

// ---------------- final decoder output (t = TDEC-1) ---------------------------
__global__ void __launch_bounds__(256)
dec_out_kernel(const __nv_bfloat16* __restrict__ hhi,
               const __nv_bfloat16* __restrict__ hlo,
               const float* __restrict__ linW,
               const float* __restrict__ linb,
               float* __restrict__ out, int t)
{
    const int b    = blockIdx.x * 8 + (threadIdx.x >> 5);
    const int lane = threadIdx.x & 31;
    const size_t base = (size_t)b * H;
    float s = 0.0f;
#pragma unroll
    for (int k = lane; k < H; k += 32) {
        float hv = __bfloat162float(hhi[base + k]) + __bfloat162float(hlo[base + k]);
        s = fmaf(hv, linW[k], s);
    }
#pragma unroll
    for (int o = 16; o; o >>= 1)
        s += __shfl_xor_sync(0xffffffffu, s, o);
    if (lane == 0)
        out[b * TDEC + t] = s + linb[0];
}

// ---------------- launch ------------------------------------------------------
extern "C" void kernel_launch(void* const* d_in, const int* in_sizes, int n_in,
                              void* d_out, int out_size)
{
    (void)in_sizes; (void)n_in; (void)out_size;
    const float* inputs = (const float*)d_in[0];
    // d_in[1] = targets (unused: teacher_forcing_ratio == 0)
    const float* encWih = (const float*)d_in[2];
    const float* encWhh = (const float*)d_in[3];
    const float* encB   = (const float*)d_in[4];
    const float* decWih = (const float*)d_in[5];
    const float* decWhh = (const float*)d_in[6];
    const float* decB   = (const float*)d_in[7];
    const float* linW   = (const float*)d_in[8];
    const float* linB   = (const float*)d_in[9];
    float* out = (float*)d_out;

    cudaFuncSetAttribute(lstm_step_kernel,
                         cudaFuncAttributeMaxDynamicSharedMemorySize, SMEM_DYN);

    __nv_bfloat16 *hhi[2], *hlo[2], *whiE, *wloE, *whiD, *wloD;
    float* xp;
    cudaGetSymbolAddress((void**)&hhi[0], g_hhi0);
    cudaGetSymbolAddress((void**)&hhi[1], g_hhi1);
    cudaGetSymbolAddress((void**)&hlo[0], g_hlo0);
    cudaGetSymbolAddress((void**)&hlo[1], g_hlo1);
    cudaGetSymbolAddress((void**)&whiE, g_whi_e);
    cudaGetSymbolAddress((void**)&wloE, g_wlo_e);
    cudaGetSymbolAddress((void**)&whiD, g_whi_d);
    cudaGetSymbolAddress((void**)&wloD, g_wlo_d);
    cudaGetSymbolAddress((void**)&xp, g_x);

    pack_w_kernel<<<4096, 256>>>(encWhh, whiE, wloE);
    pack_w_kernel<<<4096, 256>>>(decWhh, whiD, wloD);
    zero_state_kernel<<<(B * H) / 256, 256>>>();

    const dim3 grid(32, 8);   // nt x mt = 256 CTAs

    int s = 0;
    for (int t = 0; t < TENC; t++, s++) {
        lstm_step_kernel<<<grid, NTHREADS, SMEM_DYN>>>(
            hhi[s & 1], hlo[s & 1], hhi[(s & 1) ^ 1], hlo[(s & 1) ^ 1],
            whiE, wloE, encWih, encB, inputs, TENC, t,
            0, linW, linB, out, 0);
    }

    seed_x_kernel<<<2, 256>>>(inputs);

    for (int t = 0; t < TDEC; t++, s++) {
        const int xmode = (t > 0) ? 1 : 0;
        lstm_step_kernel<<<grid, NTHREADS, SMEM_DYN>>>(
            hhi[s & 1], hlo[s & 1], hhi[(s & 1) ^ 1], hlo[(s & 1) ^ 1],
            whiD, wloD, decWih, decB, xp, 1, 0,
            xmode, linW, linB, out, t - 1);
    }

    // final column: out[:, TDEC-1] = lin(h_final)
    dec_out_kernel<<<B / 8, 256>>>(hhi[s & 1], hlo[s & 1], linW, linB,
                                   out, TDEC - 1);
}

// round 11
// speedup vs baseline: 1.2998x; 1.2625x over previous
#include <cuda_runtime.h>
#include <cuda_bf16.h>
#include <stdint.h>
#include <math.h>

#define B      512
#define H      512
#define TENC   512
#define TDEC   128
#define TTOT   640
#define GROUP  32            // CTAs per mt barrier group
#define NMT    4

#define ASTAGE_BYTES 32768   // hh 16KB + hl 16KB per pair-stage
#define NASTAGE 3
#define WOFF   (NASTAGE * ASTAGE_BYTES)        // 98304
#define SMEM_DYN (WOFF + 16 * 8192 + 1024)     // 230400 <= 232448

// ---------------- persistent device state (no allocation allowed) ----------
static __device__ __align__(16) __nv_bfloat16 g_hhi0[B * H];
static __device__ __align__(16) __nv_bfloat16 g_hhi1[B * H];
static __device__ __align__(16) __nv_bfloat16 g_hlo0[B * H];
static __device__ __align__(16) __nv_bfloat16 g_hlo1[B * H];
static __device__ float g_xpart[GROUP * B];            // [nt][b] partial lin(h)
static __device__ __align__(16) __nv_bfloat16 g_whi_e[2048 * 512];
static __device__ __align__(16) __nv_bfloat16 g_wlo_e[2048 * 512];
static __device__ __align__(16) __nv_bfloat16 g_whi_d[2048 * 512];
static __device__ __align__(16) __nv_bfloat16 g_wlo_d[2048 * 512];
static __device__ unsigned g_cnt[NMT * 32];            // 128B-spaced counters
static __device__ volatile unsigned g_sense[NMT * 32];

// ---------------- helpers ----------------------------------------------------
__device__ __forceinline__ uint32_t smem_u32(const void* p) {
    uint32_t a;
    asm("{ .reg .u64 t; cvta.to.shared.u64 t, %1; cvt.u32.u64 %0, t; }"
        : "=r"(a) : "l"(p));
    return a;
}
__device__ __forceinline__ void cp16(uint32_t dst, const void* src) {
    asm volatile("cp.async.cg.shared.global [%0], [%1], 16;" :: "r"(dst), "l"(src));
}
__device__ __forceinline__ void cp_commit() {
    asm volatile("cp.async.commit_group;" ::: "memory");
}
__device__ __forceinline__ void cp_wait1() {
    asm volatile("cp.async.wait_group 1;" ::: "memory");
}
__device__ __forceinline__ void cp_wait0() {
    asm volatile("cp.async.wait_group 0;" ::: "memory");
}
__device__ __forceinline__ void ldsm_x4(uint32_t& r0, uint32_t& r1,
                                        uint32_t& r2, uint32_t& r3, uint32_t addr) {
    asm volatile("ldmatrix.sync.aligned.m8n8.x4.shared.b16 {%0,%1,%2,%3}, [%4];"
                 : "=r"(r0), "=r"(r1), "=r"(r2), "=r"(r3) : "r"(addr));
}
__device__ __forceinline__ void mma_bf16(float* c, const uint32_t* a,
                                         uint32_t b0, uint32_t b1) {
    asm volatile(
        "mma.sync.aligned.m16n8k16.row.col.f32.bf16.bf16.f32 "
        "{%0,%1,%2,%3}, {%4,%5,%6,%7}, {%8,%9}, {%0,%1,%2,%3};"
        : "+f"(c[0]), "+f"(c[1]), "+f"(c[2]), "+f"(c[3])
        : "r"(a[0]), "r"(a[1]), "r"(a[2]), "r"(a[3]), "r"(b0), "r"(b1));
}
__device__ __forceinline__ float sigf(float x) { return 1.0f / (1.0f + __expf(-x)); }
__device__ __forceinline__ float tanhe(float x) {
    return __fmaf_rn(2.0f, sigf(2.0f * x), -1.0f);
}

// Sense-reversing barrier across the 32 CTAs of one mt group.
__device__ __forceinline__ void group_barrier(int mt, unsigned want) {
    __syncthreads();
    if (threadIdx.x == 0) {
        __threadfence();                       // release h / xpart writes
        if (atomicAdd(&g_cnt[mt * 32], 1u) == GROUP - 1u) {
            g_cnt[mt * 32] = 0u;
            __threadfence();
            g_sense[mt * 32] = want;
        } else {
            while (g_sense[mt * 32] != want) __nanosleep(32);
        }
        __threadfence();                       // acquire
    }
    __syncthreads();
}

// ---------------- prologue kernels -------------------------------------------
// Repack W (2048,512): packed row n' = nt*64 + g*16 + jl  <->  n = g*512 + nt*16 + jl
__global__ void pack_w_kernel(const float* __restrict__ W,
                              __nv_bfloat16* __restrict__ whi,
                              __nv_bfloat16* __restrict__ wlo) {
    int idx = blockIdx.x * 256 + threadIdx.x;
    int np = idx >> 9, k = idx & 511;
    int nt = np >> 6, r = np & 63;
    int n = (r >> 4) * 512 + nt * 16 + (r & 15);
    float w = W[n * 512 + k];
    __nv_bfloat16 hi = __float2bfloat16_rn(w);
    whi[idx] = hi;
    wlo[idx] = __float2bfloat16_rn(w - __bfloat162float(hi));
}

__global__ void zero_state_kernel() {
    int i = blockIdx.x * 256 + threadIdx.x;
    if (i < B * H) {
        g_hhi0[i] = __float2bfloat16(0.0f);
        g_hlo0[i] = __float2bfloat16(0.0f);
    }
}

// ---------------- the persistent encoder-decoder kernel ----------------------
__global__ void __launch_bounds__(256, 1)
lstm_persistent(const float* __restrict__ inputs,
                const __nv_bfloat16* __restrict__ whiE, const __nv_bfloat16* __restrict__ wloE,
                const __nv_bfloat16* __restrict__ whiD, const __nv_bfloat16* __restrict__ wloD,
                const float* __restrict__ encWih, const float* __restrict__ encB,
                const float* __restrict__ decWih, const float* __restrict__ decB,
                const float* __restrict__ linW, const float* __restrict__ linb,
                float* __restrict__ out)
{
    extern __shared__ char dsmem[];
    uint32_t raw = smem_u32(dsmem);
    uint32_t sb  = (raw + 1023) & ~1023u;
    char* sp     = dsmem + (sb - raw);
    float* zs    = (float*)sp;     // 128 x 68 f32 (34 KB), reuses A stages post-sync

    const int tid  = threadIdx.x;
    const int wid  = tid >> 5;
    const int lane = tid & 31;
    const int wm   = wid >> 1;     // 0..3 : 32-row warp tile
    const int wn   = wid & 1;      // 0..1 : 32-col warp tile
    const int nt   = blockIdx.x;   // 0..31
    const int mt   = blockIdx.y;   // 0..3
    const int brow0 = mt * 128;

    // ---- staging map: thread covers 16B in 4 rows of a 128x64 chunk ---------
    const int gr  = tid >> 3;             // 0..31
    const int gce = (tid & 7) * 8;        // element col
    uint32_t soA[4];
#pragma unroll
    for (int i = 0; i < 4; i++) {
        int row = gr + 32 * i;
        soA[i] = (uint32_t)row * 128u + (((uint32_t)gce * 2) ^ (uint32_t)((row & 7) << 4));
    }

    // ---- ldmatrix addressing --------------------------------------------------
    const int lrow = lane & 15;
    const uint32_t kb2 = (uint32_t)((lane >> 4) * 16);
    uint32_t aoff[2], axor[2], boff[2], bxor[2];
#pragma unroll
    for (int mi = 0; mi < 2; mi++) {
        int r = wm * 32 + mi * 16 + lrow;
        aoff[mi] = (uint32_t)r * 128u;
        axor[mi] = (uint32_t)((r & 7) << 4);
    }
#pragma unroll
    for (int nb = 0; nb < 2; nb++) {
        int r = wn * 32 + nb * 16 + lrow;
        boff[nb] = (uint32_t)r * 128u;
        bxor[nb] = (uint32_t)((r & 7) << 4);
    }

    // ---- load W tiles into smem (16 tiles x 8KB: Wh kc0..7, Wl kc0..7) ------
    auto load_w = [&](const __nv_bfloat16* wh, const __nv_bfloat16* wl) {
#pragma unroll 4
        for (int j = 0; j < 32; ++j) {
            int slot = tid + j * 256;
            int tile = slot >> 9;
            int win  = slot & 511;
            int row  = win >> 3;
            int ce   = (win & 7) * 8;
            const __nv_bfloat16* src = ((tile >> 3) ? wl : wh)
                + (size_t)(nt * 64 + row) * 512 + (tile & 7) * 64 + ce;
            uint32_t dst = sb + WOFF + (uint32_t)tile * 8192u
                + (uint32_t)row * 128u
                + (((uint32_t)ce * 2u) ^ (uint32_t)((row & 7) << 4));
            cp16(dst, src);
        }
        cp_commit();
        cp_wait0();
        __syncthreads();
    };

    load_w(whiE, wloE);
    const float* Wih  = encWih;
    const float* bias = encB;

    // ---- epilogue constants ----------------------------------------------------
    const int q    = tid & 3;
    const int eml  = tid >> 2;            // 0..63
    const int jl0  = q * 4;
    const int jh0  = nt * 16 + jl0;
    const float lbv = __ldg(linb);
    const float4 lw = __ldg((const float4*)(linW + jh0));

    float creg[2][4];                     // cell state lives in registers
#pragma unroll
    for (int r = 0; r < 2; r++)
#pragma unroll
        for (int j = 0; j < 4; j++) creg[r][j] = 0.0f;

    for (int t = 0; t < TTOT; ++t) {
        if (t == TENC) {
            load_w(whiD, wloD);
            Wih = decWih; bias = decB;
        }
        const __nv_bfloat16* hi = (t & 1) ? g_hhi1 : g_hhi0;
        const __nv_bfloat16* lo = (t & 1) ? g_hlo1 : g_hlo0;
        __nv_bfloat16* hio = (t & 1) ? g_hhi0 : g_hhi1;
        __nv_bfloat16* loo = (t & 1) ? g_hlo0 : g_hlo1;

        float acc[2][4][4];
#pragma unroll
        for (int mi = 0; mi < 2; mi++)
#pragma unroll
            for (int ni = 0; ni < 4; ni++)
#pragma unroll
                for (int qq = 0; qq < 4; qq++) acc[mi][ni][qq] = 0.0f;

        auto issue_pair = [&](int p) {
            const uint32_t ab = sb + (uint32_t)(p % 3) * ASTAGE_BYTES;
            const int koff = p * 64;
#pragma unroll
            for (int i = 0; i < 4; ++i) {
                const int row = gr + 32 * i;
                const size_t go = (size_t)(brow0 + row) * 512 + koff + gce;
                cp16(ab + soA[i],          hi + go);
                cp16(ab + 16384u + soA[i], lo + go);
            }
            cp_commit();
        };

        auto compute_pair = [&](int p) {
            const uint32_t ab  = sb + (uint32_t)(p % 3) * ASTAGE_BYTES;
            const uint32_t alb = ab + 16384u;
            const uint32_t whb = sb + WOFF + (uint32_t)p * 8192u;
            const uint32_t wlb = whb + 65536u;
#pragma unroll
            for (int s = 0; s < 4; ++s) {
                const uint32_t kb = (uint32_t)(s * 32);
                uint32_t ah[2][4], al[2][4];
#pragma unroll
                for (int mi = 0; mi < 2; ++mi) {
                    const uint32_t off = aoff[mi] + ((kb + kb2) ^ axor[mi]);
                    ldsm_x4(ah[mi][0], ah[mi][1], ah[mi][2], ah[mi][3], ab  + off);
                    ldsm_x4(al[mi][0], al[mi][1], al[mi][2], al[mi][3], alb + off);
                }
                uint32_t bh[4][2], bl[4][2];
#pragma unroll
                for (int nb = 0; nb < 2; ++nb) {
                    const uint32_t off = boff[nb] + ((kb + kb2) ^ bxor[nb]);
                    uint32_t q0, q1, q2, q3;
                    ldsm_x4(q0, q1, q2, q3, whb + off);
                    bh[nb*2][0] = q0; bh[nb*2][1] = q2;
                    bh[nb*2+1][0] = q1; bh[nb*2+1][1] = q3;
                    ldsm_x4(q0, q1, q2, q3, wlb + off);
                    bl[nb*2][0] = q0; bl[nb*2][1] = q2;
                    bl[nb*2+1][0] = q1; bl[nb*2+1][1] = q3;
                }
#pragma unroll
                for (int mi = 0; mi < 2; ++mi)
#pragma unroll
                    for (int ni = 0; ni < 4; ++ni) {
                        mma_bf16(acc[mi][ni], ah[mi], bh[ni][0], bh[ni][1]);
                        mma_bf16(acc[mi][ni], ah[mi], bl[ni][0], bl[ni][1]);
                        mma_bf16(acc[mi][ni], al[mi], bh[ni][0], bh[ni][1]);
                    }
            }
        };

        // pipeline: 8 pairs, 3 stages
        issue_pair(0);
        issue_pair(1);
        for (int p = 0; p < 8; ++p) {
            cp_wait1();
            __syncthreads();
            if (p + 2 < 8) issue_pair(p + 2);
            else           cp_commit();       // keep group count advancing
            compute_pair(p);
        }
        cp_wait0();
        __syncthreads();

        // ---- accum -> zs (stride 68) -----------------------------------------
        {
            const int g  = lane >> 2;
            const int t2 = (lane & 3) * 2;
#pragma unroll
            for (int mi = 0; mi < 2; mi++)
#pragma unroll
                for (int ni = 0; ni < 4; ni++) {
                    const int row = wm * 32 + mi * 16 + g;
                    const int col = wn * 32 + ni * 8 + t2;
                    *(float2*)(zs + row * 68 + col) =
                        make_float2(acc[mi][ni][0], acc[mi][ni][1]);
                    *(float2*)(zs + (row + 8) * 68 + col) =
                        make_float2(acc[mi][ni][2], acc[mi][ni][3]);
                }
        }
        __syncthreads();

        // ---- gate pass: thread quads, 2 rows each ------------------------------
        const float4 wi0 = __ldg((const float4*)(Wih + jh0));
        const float4 wi1 = __ldg((const float4*)(Wih + 512 + jh0));
        const float4 wi2 = __ldg((const float4*)(Wih + 1024 + jh0));
        const float4 wi3 = __ldg((const float4*)(Wih + 1536 + jh0));
        const float4 bq0 = __ldg((const float4*)(bias + jh0));
        const float4 bq1 = __ldg((const float4*)(bias + 512 + jh0));
        const float4 bq2 = __ldg((const float4*)(bias + 1024 + jh0));
        const float4 bq3 = __ldg((const float4*)(bias + 1536 + jh0));

#pragma unroll
        for (int rr = 0; rr < 2; ++rr) {
            const int r = eml + rr * 64;
            const int b = brow0 + r;

            float xv;
            if (t < TENC) {
                xv = __ldg(inputs + (size_t)b * 512 + t);
            } else if (t == TENC) {
                xv = __ldg(inputs + (size_t)b * 512 + 511);
            } else {
                float s = 0.0f;
#pragma unroll
                for (int i = 0; i < 8; ++i)
                    s += g_xpart[(q * 8 + i) * B + b];
                s += __shfl_xor_sync(0xffffffffu, s, 1);
                s += __shfl_xor_sync(0xffffffffu, s, 2);
                xv = s + lbv;
                if (nt == 0 && q == 0)
                    out[(size_t)b * TDEC + (t - TENC - 1)] = xv;
            }

            float zi[4], zf[4], zg[4], zo[4];
            *(float4*)zi = *(const float4*)(zs + r * 68 +      jl0);
            *(float4*)zf = *(const float4*)(zs + r * 68 + 16 + jl0);
            *(float4*)zg = *(const float4*)(zs + r * 68 + 32 + jl0);
            *(float4*)zo = *(const float4*)(zs + r * 68 + 48 + jl0);

            const float* w0 = (const float*)&wi0; const float* b0 = (const float*)&bq0;
            const float* w1 = (const float*)&wi1; const float* b1 = (const float*)&bq1;
            const float* w2 = (const float*)&wi2; const float* b2 = (const float*)&bq2;
            const float* w3 = (const float*)&wi3; const float* b3 = (const float*)&bq3;

            float hv[4];
#pragma unroll
            for (int j = 0; j < 4; ++j) {
                const float vi = zi[j] + xv * w0[j] + b0[j];
                const float vf = zf[j] + xv * w1[j] + b1[j];
                const float vg = zg[j] + xv * w2[j] + b2[j];
                const float vo = zo[j] + xv * w3[j] + b3[j];
                const float cn = sigf(vf) * creg[rr][j] + sigf(vi) * tanhe(vg);
                creg[rr][j] = cn;
                hv[j] = sigf(vo) * tanhe(cn);
            }

            __nv_bfloat162 hh01 = __floats2bfloat162_rn(hv[0], hv[1]);
            __nv_bfloat162 hh23 = __floats2bfloat162_rn(hv[2], hv[3]);
            float l0 = hv[0] - __bfloat162float(__low2bfloat16(hh01));
            float l1 = hv[1] - __bfloat162float(__high2bfloat16(hh01));
            float l2 = hv[2] - __bfloat162float(__low2bfloat16(hh23));
            float l3 = hv[3] - __bfloat162float(__high2bfloat16(hh23));
            __nv_bfloat162 hl01 = __floats2bfloat162_rn(l0, l1);
            __nv_bfloat162 hl23 = __floats2bfloat162_rn(l2, l3);
            uint2 hp, lp;
            hp.x = *(uint32_t*)&hh01; hp.y = *(uint32_t*)&hh23;
            lp.x = *(uint32_t*)&hl01; lp.y = *(uint32_t*)&hl23;
            const size_t oidx = (size_t)b * H + jh0;
            *(uint2*)(hio + oidx) = hp;
            *(uint2*)(loo + oidx) = lp;

            if (t >= TENC) {   // partial lin(h_t) for the next step's x
                float s = hv[0] * lw.x + hv[1] * lw.y + hv[2] * lw.z + hv[3] * lw.w;
                s += __shfl_xor_sync(0xffffffffu, s, 1);
                s += __shfl_xor_sync(0xffffffffu, s, 2);
                if (q == 0) g_xpart[nt * B + b] = s;
            }
        }

        group_barrier(mt, (unsigned)((t + 1) & 1));
    }

    // ---- final output column: out[:, 127] = lin(h_final) -----------------------
    if (nt == 0 && tid < 128) {
        const int b = brow0 + tid;
        float s = lbv;
#pragma unroll
        for (int i = 0; i < 32; ++i) s += g_xpart[i * B + b];
        out[(size_t)b * TDEC + (TDEC - 1)] = s;
    }
}

// ---------------- launch ------------------------------------------------------
extern "C" void kernel_launch(void* const* d_in, const int* in_sizes, int n_in,
                              void* d_out, int out_size)
{
    (void)in_sizes; (void)n_in; (void)out_size;
    const float* inputs = (const float*)d_in[0];
    // d_in[1] = targets (unused: teacher_forcing_ratio == 0)
    const float* encWih = (const float*)d_in[2];
    const float* encWhh = (const float*)d_in[3];
    const float* encB   = (const float*)d_in[4];
    const float* decWih = (const float*)d_in[5];
    const float* decWhh = (const float*)d_in[6];
    const float* decB   = (const float*)d_in[7];
    const float* linW   = (const float*)d_in[8];
    const float* linB   = (const float*)d_in[9];
    float* out = (float*)d_out;

    cudaFuncSetAttribute(lstm_persistent,
                         cudaFuncAttributeMaxDynamicSharedMemorySize, SMEM_DYN);

    __nv_bfloat16 *whiE, *wloE, *whiD, *wloD;
    cudaGetSymbolAddress((void**)&whiE, g_whi_e);
    cudaGetSymbolAddress((void**)&wloE, g_wlo_e);
    cudaGetSymbolAddress((void**)&whiD, g_whi_d);
    cudaGetSymbolAddress((void**)&wloD, g_wlo_d);

    pack_w_kernel<<<4096, 256>>>(encWhh, whiE, wloE);
    pack_w_kernel<<<4096, 256>>>(decWhh, whiD, wloD);
    zero_state_kernel<<<(B * H) / 256, 256>>>();

    lstm_persistent<<<dim3(32, 4), 256, SMEM_DYN>>>(
        inputs, whiE, wloE, whiD, wloD,
        encWih, encB, decWih, decB, linW, linB, out);
}

// round 12
// speedup vs baseline: 1.4317x; 1.1015x over previous
#include <cuda_runtime.h>
#include <cuda_bf16.h>
#include <stdint.h>
#include <math.h>

#define B      512
#define H      512
#define TENC   512
#define TDEC   128
#define TTOT   640
#define GROUP  32            // CTAs per mt barrier group
#define NMT    4
#define NTHREADS 512

#define ASTAGE_BYTES 32768   // hh 16KB + hl 16KB per pair-stage
#define NASTAGE 3
#define WOFF   (NASTAGE * ASTAGE_BYTES)        // 98304
#define SMEM_DYN (WOFF + 16 * 8192 + 1024)     // 230400 <= 232448

// ---------------- persistent device state (no allocation allowed) ----------
static __device__ __align__(16) __nv_bfloat16 g_hhi0[B * H];
static __device__ __align__(16) __nv_bfloat16 g_hhi1[B * H];
static __device__ __align__(16) __nv_bfloat16 g_hlo0[B * H];
static __device__ __align__(16) __nv_bfloat16 g_hlo1[B * H];
static __device__ float g_xpart[GROUP * B];            // [nt][b] partial lin(h)
static __device__ __align__(16) __nv_bfloat16 g_whi_e[2048 * 512];
static __device__ __align__(16) __nv_bfloat16 g_wlo_e[2048 * 512];
static __device__ __align__(16) __nv_bfloat16 g_whi_d[2048 * 512];
static __device__ __align__(16) __nv_bfloat16 g_wlo_d[2048 * 512];
static __device__ unsigned g_cnt[NMT * 32];            // 128B-spaced counters
static __device__ volatile unsigned g_sense[NMT * 32];

// ---------------- helpers ----------------------------------------------------
__device__ __forceinline__ uint32_t smem_u32(const void* p) {
    uint32_t a;
    asm("{ .reg .u64 t; cvta.to.shared.u64 t, %1; cvt.u32.u64 %0, t; }"
        : "=r"(a) : "l"(p));
    return a;
}
__device__ __forceinline__ void cp16(uint32_t dst, const void* src) {
    asm volatile("cp.async.cg.shared.global [%0], [%1], 16;" :: "r"(dst), "l"(src));
}
__device__ __forceinline__ void cp_commit() {
    asm volatile("cp.async.commit_group;" ::: "memory");
}
__device__ __forceinline__ void cp_wait1() {
    asm volatile("cp.async.wait_group 1;" ::: "memory");
}
__device__ __forceinline__ void cp_wait0() {
    asm volatile("cp.async.wait_group 0;" ::: "memory");
}
__device__ __forceinline__ void ldsm_x4(uint32_t& r0, uint32_t& r1,
                                        uint32_t& r2, uint32_t& r3, uint32_t addr) {
    asm volatile("ldmatrix.sync.aligned.m8n8.x4.shared.b16 {%0,%1,%2,%3}, [%4];"
                 : "=r"(r0), "=r"(r1), "=r"(r2), "=r"(r3) : "r"(addr));
}
__device__ __forceinline__ void mma_bf16(float* c, const uint32_t* a,
                                         uint32_t b0, uint32_t b1) {
    asm volatile(
        "mma.sync.aligned.m16n8k16.row.col.f32.bf16.bf16.f32 "
        "{%0,%1,%2,%3}, {%4,%5,%6,%7}, {%8,%9}, {%0,%1,%2,%3};"
        : "+f"(c[0]), "+f"(c[1]), "+f"(c[2]), "+f"(c[3])
        : "r"(a[0]), "r"(a[1]), "r"(a[2]), "r"(a[3]), "r"(b0), "r"(b1));
}
__device__ __forceinline__ float sigf(float x) { return 1.0f / (1.0f + __expf(-x)); }
__device__ __forceinline__ float tanhe(float x) {
    return __fmaf_rn(2.0f, sigf(2.0f * x), -1.0f);
}

// Sense-reversing barrier across the 32 CTAs of one mt group.
__device__ __forceinline__ void group_barrier(int mt, unsigned want) {
    __syncthreads();
    if (threadIdx.x == 0) {
        __threadfence();                       // release h / xpart writes
        if (atomicAdd(&g_cnt[mt * 32], 1u) == GROUP - 1u) {
            g_cnt[mt * 32] = 0u;
            __threadfence();
            g_sense[mt * 32] = want;
        } else {
            while (g_sense[mt * 32] != want) __nanosleep(32);
        }
        __threadfence();                       // acquire
    }
    __syncthreads();
}

// ---------------- prologue kernels -------------------------------------------
// Repack W (2048,512): packed row n' = nt*64 + g*16 + jl  <->  n = g*512 + nt*16 + jl
__global__ void pack_w_kernel(const float* __restrict__ W,
                              __nv_bfloat16* __restrict__ whi,
                              __nv_bfloat16* __restrict__ wlo) {
    int idx = blockIdx.x * 256 + threadIdx.x;
    int np = idx >> 9, k = idx & 511;
    int nt = np >> 6, r = np & 63;
    int n = (r >> 4) * 512 + nt * 16 + (r & 15);
    float w = W[n * 512 + k];
    __nv_bfloat16 hi = __float2bfloat16_rn(w);
    whi[idx] = hi;
    wlo[idx] = __float2bfloat16_rn(w - __bfloat162float(hi));
}

__global__ void zero_state_kernel() {
    int i = blockIdx.x * 256 + threadIdx.x;
    if (i < B * H) {
        g_hhi0[i] = __float2bfloat16(0.0f);
        g_hlo0[i] = __float2bfloat16(0.0f);
    }
}

// ---------------- the persistent encoder-decoder kernel ----------------------
__global__ void __launch_bounds__(NTHREADS, 1)
lstm_persistent(const float* __restrict__ inputs,
                const __nv_bfloat16* __restrict__ whiE, const __nv_bfloat16* __restrict__ wloE,
                const __nv_bfloat16* __restrict__ whiD, const __nv_bfloat16* __restrict__ wloD,
                const float* __restrict__ encWih, const float* __restrict__ encB,
                const float* __restrict__ decWih, const float* __restrict__ decB,
                const float* __restrict__ linW, const float* __restrict__ linb,
                float* __restrict__ out)
{
    extern __shared__ char dsmem[];
    uint32_t raw = smem_u32(dsmem);
    uint32_t sb  = (raw + 1023) & ~1023u;
    char* sp     = dsmem + (sb - raw);
    float* zs    = (float*)sp;     // 128 x 68 f32 (34 KB), reuses A stages post-sync

    const int tid  = threadIdx.x;
    const int wid  = tid >> 5;
    const int lane = tid & 31;
    const int wm   = wid >> 2;     // 0..3 : 32-row warp tile
    const int wn   = wid & 3;      // 0..3 : 16-col warp tile
    const int nt   = blockIdx.x;   // 0..31
    const int mt   = blockIdx.y;   // 0..3
    const int brow0 = mt * 128;

    // ---- staging map: thread covers 16B in 2 rows of a 128x64 chunk ---------
    const int gr  = tid >> 3;             // 0..63
    const int gce = (tid & 7) * 8;        // element col
    uint32_t soA[2];
#pragma unroll
    for (int i = 0; i < 2; i++) {
        int row = gr + 64 * i;
        soA[i] = (uint32_t)row * 128u + (((uint32_t)gce * 2) ^ (uint32_t)((row & 7) << 4));
    }

    // ---- ldmatrix addressing --------------------------------------------------
    const int lrow = lane & 15;
    const uint32_t kb2 = (uint32_t)((lane >> 4) * 16);
    uint32_t aoff[2], axor[2], boff, bxor;
#pragma unroll
    for (int mi = 0; mi < 2; mi++) {
        int r = wm * 32 + mi * 16 + lrow;
        aoff[mi] = (uint32_t)r * 128u;
        axor[mi] = (uint32_t)((r & 7) << 4);
    }
    {
        int r = wn * 16 + lrow;
        boff = (uint32_t)r * 128u;
        bxor = (uint32_t)((r & 7) << 4);
    }

    // ---- load W tiles into smem (16 tiles x 8KB: Wh kc0..7, Wl kc0..7) ------
    auto load_w = [&](const __nv_bfloat16* wh, const __nv_bfloat16* wl) {
#pragma unroll 4
        for (int j = 0; j < 16; ++j) {
            int slot = tid + j * NTHREADS;
            int tile = slot >> 9;
            int win  = slot & 511;
            int row  = win >> 3;
            int ce   = (win & 7) * 8;
            const __nv_bfloat16* src = ((tile >> 3) ? wl : wh)
                + (size_t)(nt * 64 + row) * 512 + (tile & 7) * 64 + ce;
            uint32_t dst = sb + WOFF + (uint32_t)tile * 8192u
                + (uint32_t)row * 128u
                + (((uint32_t)ce * 2u) ^ (uint32_t)((row & 7) << 4));
            cp16(dst, src);
        }
        cp_commit();
        cp_wait0();
        __syncthreads();
    };

    load_w(whiE, wloE);
    const float* Wih  = encWih;
    const float* bias = encB;

    // ---- epilogue constants ----------------------------------------------------
    const int q    = tid & 3;
    const int eml  = tid >> 2;            // 0..127 (batch row in tile)
    const int jl0  = q * 4;
    const int jh0  = nt * 16 + jl0;
    const float lbv = __ldg(linb);
    const float4 lw = __ldg((const float4*)(linW + jh0));

    float creg[4];                        // cell state lives in registers
#pragma unroll
    for (int j = 0; j < 4; j++) creg[j] = 0.0f;

    for (int t = 0; t < TTOT; ++t) {
        if (t == TENC) {
            load_w(whiD, wloD);
            Wih = decWih; bias = decB;
        }
        const __nv_bfloat16* hi = (t & 1) ? g_hhi1 : g_hhi0;
        const __nv_bfloat16* lo = (t & 1) ? g_hlo1 : g_hlo0;
        __nv_bfloat16* hio = (t & 1) ? g_hhi0 : g_hhi1;
        __nv_bfloat16* loo = (t & 1) ? g_hlo0 : g_hlo1;

        float acc[2][2][4];
#pragma unroll
        for (int mi = 0; mi < 2; mi++)
#pragma unroll
            for (int ni = 0; ni < 2; ni++)
#pragma unroll
                for (int qq = 0; qq < 4; qq++) acc[mi][ni][qq] = 0.0f;

        auto issue_pair = [&](int p) {
            const uint32_t ab = sb + (uint32_t)(p % 3) * ASTAGE_BYTES;
            const int koff = p * 64;
#pragma unroll
            for (int i = 0; i < 2; ++i) {
                const int row = gr + 64 * i;
                const size_t go = (size_t)(brow0 + row) * 512 + koff + gce;
                cp16(ab + soA[i],          hi + go);
                cp16(ab + 16384u + soA[i], lo + go);
            }
            cp_commit();
        };

        auto compute_pair = [&](int p) {
            const uint32_t ab  = sb + (uint32_t)(p % 3) * ASTAGE_BYTES;
            const uint32_t alb = ab + 16384u;
            const uint32_t whb = sb + WOFF + (uint32_t)p * 8192u;
            const uint32_t wlb = whb + 65536u;
#pragma unroll
            for (int s = 0; s < 4; ++s) {
                const uint32_t kb = (uint32_t)(s * 32);
                uint32_t ah[2][4], al[2][4];
#pragma unroll
                for (int mi = 0; mi < 2; ++mi) {
                    const uint32_t off = aoff[mi] + ((kb + kb2) ^ axor[mi]);
                    ldsm_x4(ah[mi][0], ah[mi][1], ah[mi][2], ah[mi][3], ab  + off);
                    ldsm_x4(al[mi][0], al[mi][1], al[mi][2], al[mi][3], alb + off);
                }
                uint32_t bh[2][2], bl[2][2];
                {
                    const uint32_t off = boff + ((kb + kb2) ^ bxor);
                    uint32_t q0, q1, q2, q3;
                    ldsm_x4(q0, q1, q2, q3, whb + off);
                    bh[0][0] = q0; bh[0][1] = q2;
                    bh[1][0] = q1; bh[1][1] = q3;
                    ldsm_x4(q0, q1, q2, q3, wlb + off);
                    bl[0][0] = q0; bl[0][1] = q2;
                    bl[1][0] = q1; bl[1][1] = q3;
                }
#pragma unroll
                for (int mi = 0; mi < 2; ++mi)
#pragma unroll
                    for (int ni = 0; ni < 2; ++ni) {
                        mma_bf16(acc[mi][ni], ah[mi], bh[ni][0], bh[ni][1]);
                        mma_bf16(acc[mi][ni], ah[mi], bl[ni][0], bl[ni][1]);
                        mma_bf16(acc[mi][ni], al[mi], bh[ni][0], bh[ni][1]);
                    }
            }
        };

        // pipeline: 8 pairs, 3 stages
        issue_pair(0);
        issue_pair(1);
        for (int p = 0; p < 8; ++p) {
            cp_wait1();
            __syncthreads();
            if (p + 2 < 8) issue_pair(p + 2);
            else           cp_commit();       // keep group count advancing
            compute_pair(p);
        }
        cp_wait0();
        __syncthreads();

        // ---- accum -> zs (stride 68) -----------------------------------------
        {
            const int g  = lane >> 2;
            const int t2 = (lane & 3) * 2;
#pragma unroll
            for (int mi = 0; mi < 2; mi++)
#pragma unroll
                for (int ni = 0; ni < 2; ni++) {
                    const int row = wm * 32 + mi * 16 + g;
                    const int col = wn * 16 + ni * 8 + t2;
                    *(float2*)(zs + row * 68 + col) =
                        make_float2(acc[mi][ni][0], acc[mi][ni][1]);
                    *(float2*)(zs + (row + 8) * 68 + col) =
                        make_float2(acc[mi][ni][2], acc[mi][ni][3]);
                }
        }
        __syncthreads();

        // ---- gate pass: one row x 4 jh per thread -------------------------------
        const float4 wi0 = __ldg((const float4*)(Wih + jh0));
        const float4 wi1 = __ldg((const float4*)(Wih + 512 + jh0));
        const float4 wi2 = __ldg((const float4*)(Wih + 1024 + jh0));
        const float4 wi3 = __ldg((const float4*)(Wih + 1536 + jh0));
        const float4 bq0 = __ldg((const float4*)(bias + jh0));
        const float4 bq1 = __ldg((const float4*)(bias + 512 + jh0));
        const float4 bq2 = __ldg((const float4*)(bias + 1024 + jh0));
        const float4 bq3 = __ldg((const float4*)(bias + 1536 + jh0));

        {
            const int r = eml;
            const int b = brow0 + r;

            float xv;
            if (t < TENC) {
                xv = __ldg(inputs + (size_t)b * 512 + t);
            } else if (t == TENC) {
                xv = __ldg(inputs + (size_t)b * 512 + 511);
            } else {
                float s = 0.0f;
#pragma unroll
                for (int i = 0; i < 8; ++i)
                    s += g_xpart[(q * 8 + i) * B + b];
                s += __shfl_xor_sync(0xffffffffu, s, 1);
                s += __shfl_xor_sync(0xffffffffu, s, 2);
                xv = s + lbv;
                if (nt == 0 && q == 0)
                    out[(size_t)b * TDEC + (t - TENC - 1)] = xv;
            }

            float zi[4], zf[4], zg[4], zo[4];
            *(float4*)zi = *(const float4*)(zs + r * 68 +      jl0);
            *(float4*)zf = *(const float4*)(zs + r * 68 + 16 + jl0);
            *(float4*)zg = *(const float4*)(zs + r * 68 + 32 + jl0);
            *(float4*)zo = *(const float4*)(zs + r * 68 + 48 + jl0);

            const float* w0 = (const float*)&wi0; const float* b0 = (const float*)&bq0;
            const float* w1 = (const float*)&wi1; const float* b1 = (const float*)&bq1;
            const float* w2 = (const float*)&wi2; const float* b2 = (const float*)&bq2;
            const float* w3 = (const float*)&wi3; const float* b3 = (const float*)&bq3;

            float hv[4];
#pragma unroll
            for (int j = 0; j < 4; ++j) {
                const float vi = zi[j] + xv * w0[j] + b0[j];
                const float vf = zf[j] + xv * w1[j] + b1[j];
                const float vg = zg[j] + xv * w2[j] + b2[j];
                const float vo = zo[j] + xv * w3[j] + b3[j];
                const float cn = sigf(vf) * creg[j] + sigf(vi) * tanhe(vg);
                creg[j] = cn;
                hv[j] = sigf(vo) * tanhe(cn);
            }

            __nv_bfloat162 hh01 = __floats2bfloat162_rn(hv[0], hv[1]);
            __nv_bfloat162 hh23 = __floats2bfloat162_rn(hv[2], hv[3]);
            float l0 = hv[0] - __bfloat162float(__low2bfloat16(hh01));
            float l1 = hv[1] - __bfloat162float(__high2bfloat16(hh01));
            float l2 = hv[2] - __bfloat162float(__low2bfloat16(hh23));
            float l3 = hv[3] - __bfloat162float(__high2bfloat16(hh23));
            __nv_bfloat162 hl01 = __floats2bfloat162_rn(l0, l1);
            __nv_bfloat162 hl23 = __floats2bfloat162_rn(l2, l3);
            uint2 hp, lp;
            hp.x = *(uint32_t*)&hh01; hp.y = *(uint32_t*)&hh23;
            lp.x = *(uint32_t*)&hl01; lp.y = *(uint32_t*)&hl23;
            const size_t oidx = (size_t)b * H + jh0;
            *(uint2*)(hio + oidx) = hp;
            *(uint2*)(loo + oidx) = lp;

            if (t >= TENC) {   // partial lin(h_t) for the next step's x
                float s = hv[0] * lw.x + hv[1] * lw.y + hv[2] * lw.z + hv[3] * lw.w;
                s += __shfl_xor_sync(0xffffffffu, s, 1);
                s += __shfl_xor_sync(0xffffffffu, s, 2);
                if (q == 0) g_xpart[nt * B + b] = s;
            }
        }

        group_barrier(mt, (unsigned)((t + 1) & 1));
    }

    // ---- final output column: out[:, 127] = lin(h_final) -----------------------
    if (nt == 0 && tid < 128) {
        const int b = brow0 + tid;
        float s = lbv;
#pragma unroll
        for (int i = 0; i < 32; ++i) s += g_xpart[i * B + b];
        out[(size_t)b * TDEC + (TDEC - 1)] = s;
    }
}

// ---------------- launch ------------------------------------------------------
extern "C" void kernel_launch(void* const* d_in, const int* in_sizes, int n_in,
                              void* d_out, int out_size)
{
    (void)in_sizes; (void)n_in; (void)out_size;
    const float* inputs = (const float*)d_in[0];
    // d_in[1] = targets (unused: teacher_forcing_ratio == 0)
    const float* encWih = (const float*)d_in[2];
    const float* encWhh = (const float*)d_in[3];
    const float* encB   = (const float*)d_in[4];
    const float* decWih = (const float*)d_in[5];
    const float* decWhh = (const float*)d_in[6];
    const float* decB   = (const float*)d_in[7];
    const float* linW   = (const float*)d_in[8];
    const float* linB   = (const float*)d_in[9];
    float* out = (float*)d_out;

    cudaFuncSetAttribute(lstm_persistent,
                         cudaFuncAttributeMaxDynamicSharedMemorySize, SMEM_DYN);

    __nv_bfloat16 *whiE, *wloE, *whiD, *wloD;
    cudaGetSymbolAddress((void**)&whiE, g_whi_e);
    cudaGetSymbolAddress((void**)&wloE, g_wlo_e);
    cudaGetSymbolAddress((void**)&whiD, g_whi_d);
    cudaGetSymbolAddress((void**)&wloD, g_wlo_d);

    pack_w_kernel<<<4096, 256>>>(encWhh, whiE, wloE);
    pack_w_kernel<<<4096, 256>>>(decWhh, whiD, wloD);
    zero_state_kernel<<<(B * H) / 256, 256>>>();

    lstm_persistent<<<dim3(32, 4), NTHREADS, SMEM_DYN>>>(
        inputs, whiE, wloE, whiD, wloD,
        encWih, encB, decWih, decB, linW, linB, out);
}